// round 13
// baseline (speedup 1.0000x reference)
#include <cuda_runtime.h>
#include <cstdint>
#include <math.h>

// Problem constants
#define G  8
#define T  4096
#define H  1024
#define E  32
#define C  64
#define GT (G*T)                       // 32768 tokens
#define GTEC ((size_t)G*(size_t)T*(size_t)E*(size_t)C)   // 67,108,864

// GEMM: 128 tokens/block, 256 threads = 4 expert-groups x 64 token-pairs
#define MTILE 128
#define KTILE 32
#define NKC   (H/KTILE)                // 32
#define GEMM_BLOCKS (GT/MTILE)         // 256
#define GTHREADS 256
#define XW 130                         // xs row stride [k][tok]
#define WW 36                          // ws row stride [k][e]

#define NTHREADS 256
#define SEL_BLOCKS  (G*E)              // 256
#define ZERO_BLOCKS 2048
#define N4H ((GTEC)/4)                 // uint4 count per half (combine|dispatch)

// Scratch (device globals; no allocations allowed)
__device__ float g_probs[G*E*T];       // probs transposed [g][e][t], 4 MB
__device__ float g_zpart[GEMM_BLOCKS];
__device__ float g_topv[G*E*C];
__device__ int   g_topt[G*E*C];

// ---------------------------------------------------------------------------
__device__ __forceinline__ void zero_half(uint4* o4, int zb, int tid)
{
    uint4 z; z.x = 0u; z.y = 0u; z.z = 0u; z.w = 0u;
    size_t i = (size_t)zb * NTHREADS + tid;
    const size_t stride = (size_t)ZERO_BLOCKS * NTHREADS;
    for (; i < N4H; i += stride) __stcs(o4 + i, z);   // 32 STG.128, streaming
}

// ---------------------------------------------------------------------------
// Kernel 1: bid<256 = R12 GEMM (bit-exact logits); bid>=256 = zero combine.
// GEMM is FMA/L1-bound (DRAM 21%), memset rides the idle write path.
// ---------------------------------------------------------------------------
__global__ void __launch_bounds__(GTHREADS)
router_k1(const float* __restrict__ x,   // [G,T,H]
          const float* __restrict__ Wm,  // [H,E]
          const float* __restrict__ bv,  // [E]
          float* __restrict__ out)
{
    const int bid = blockIdx.x;
    const int tid = threadIdx.x;

    if (bid >= GEMM_BLOCKS) {
        zero_half(reinterpret_cast<uint4*>(out), bid - GEMM_BLOCKS, tid);
        return;
    }

    const int eh  = tid >> 6;              // 0..3, uniform per warp
    const int tl2 = tid & 63;              // token-pair index 0..63

    __shared__ float xs[KTILE * XW];                 // [k][tok], 32 x 130
    __shared__ __align__(16) float ws[KTILE * WW];   // [k][e]
    __shared__ float psm[MTILE * 33];                // logits/probs staging
    __shared__ float zsm[MTILE];

    const int gtBase = bid * MTILE;
    const int g   = gtBase >> 12;
    const int tt0 = gtBase & (T - 1);
    const float* xbase = x + (size_t)gtBase * H;

    unsigned long long acc[8];
#pragma unroll
    for (int i = 0; i < 8; i++) acc[i] = 0ull;

    float4 pfx[4];
    float4 pfw;
#pragma unroll
    for (int r = 0; r < 4; r++) {
        int s  = r * GTHREADS + tid;
        int tl = s >> 3;
        int c  = s & 7;
        pfx[r] = *reinterpret_cast<const float4*>(xbase + (size_t)tl * H + c * 4);
    }
    pfw = *reinterpret_cast<const float4*>(Wm + tid * 4);

    for (int kc = 0; kc < NKC; kc++) {
        __syncthreads();
#pragma unroll
        for (int r = 0; r < 4; r++) {
            int s  = r * GTHREADS + tid;
            int tl = s >> 3;
            int c  = s & 7;
            xs[(4*c + 0) * XW + tl] = pfx[r].x;
            xs[(4*c + 1) * XW + tl] = pfx[r].y;
            xs[(4*c + 2) * XW + tl] = pfx[r].z;
            xs[(4*c + 3) * XW + tl] = pfx[r].w;
        }
        *reinterpret_cast<float4*>(ws + (tid >> 3) * WW + (tid & 7) * 4) = pfw;
        __syncthreads();

        if (kc + 1 < NKC) {
            const float* xn = xbase + (kc + 1) * KTILE;
#pragma unroll
            for (int r = 0; r < 4; r++) {
                int s  = r * GTHREADS + tid;
                int tl = s >> 3;
                int c  = s & 7;
                pfx[r] = *reinterpret_cast<const float4*>(xn + (size_t)tl * H + c * 4);
            }
            pfw = *reinterpret_cast<const float4*>(Wm + (kc + 1) * KTILE * E + tid * 4);
        }

#pragma unroll
        for (int kk = 0; kk < KTILE; kk++) {
            const float2 xv =
                *reinterpret_cast<const float2*>(xs + kk * XW + 2 * tl2);
            unsigned long long xx0, xx1;
            asm("mov.b64 %0, {%1,%1};" : "=l"(xx0) : "r"(__float_as_uint(xv.x)));
            asm("mov.b64 %0, {%1,%1};" : "=l"(xx1) : "r"(__float_as_uint(xv.y)));
            const ulonglong2* wr =
                reinterpret_cast<const ulonglong2*>(ws + kk * WW + (eh << 3));
            ulonglong2 w0 = wr[0];   // broadcast: warp-uniform address
            ulonglong2 w1 = wr[1];
            asm("fma.rn.f32x2 %0, %1, %2, %0;" : "+l"(acc[0]) : "l"(xx0), "l"(w0.x));
            asm("fma.rn.f32x2 %0, %1, %2, %0;" : "+l"(acc[1]) : "l"(xx0), "l"(w0.y));
            asm("fma.rn.f32x2 %0, %1, %2, %0;" : "+l"(acc[2]) : "l"(xx0), "l"(w1.x));
            asm("fma.rn.f32x2 %0, %1, %2, %0;" : "+l"(acc[3]) : "l"(xx0), "l"(w1.y));
            asm("fma.rn.f32x2 %0, %1, %2, %0;" : "+l"(acc[4]) : "l"(xx1), "l"(w0.x));
            asm("fma.rn.f32x2 %0, %1, %2, %0;" : "+l"(acc[5]) : "l"(xx1), "l"(w0.y));
            asm("fma.rn.f32x2 %0, %1, %2, %0;" : "+l"(acc[6]) : "l"(xx1), "l"(w1.x));
            asm("fma.rn.f32x2 %0, %1, %2, %0;" : "+l"(acc[7]) : "l"(xx1), "l"(w1.y));
        }
    }

    // ---- gather raw logits to smem (bit-exact values) ----
    {
        const int t0 = 2 * tl2, t1 = 2 * tl2 + 1;
#pragma unroll
        for (int i = 0; i < 4; i++) {
            float2 f0 = *reinterpret_cast<float2*>(&acc[i]);
            float2 f1 = *reinterpret_cast<float2*>(&acc[4 + i]);
            psm[t0 * 33 + (eh << 3) + 2*i]     = f0.x;
            psm[t0 * 33 + (eh << 3) + 2*i + 1] = f0.y;
            psm[t1 * 33 + (eh << 3) + 2*i]     = f1.x;
            psm[t1 * 33 + (eh << 3) + 2*i + 1] = f1.y;
        }
    }
    __syncthreads();

    // ---- eh==0 threads: R5's exact softmax sequence, 2 tokens each ----
    if (eh == 0) {
#pragma unroll
        for (int u = 0; u < 2; u++) {
            const int tk = 2 * tl2 + u;
            float l[E];
#pragma unroll
            for (int e = 0; e < E; e++) l[e] = psm[tk * 33 + e];
#pragma unroll
            for (int e = 0; e < E; e++) l[e] += __ldg(&bv[e]);

            float m = l[0];
#pragma unroll
            for (int e = 1; e < E; e++) m = fmaxf(m, l[e]);
            float s = 0.f;
#pragma unroll
            for (int e = 0; e < E; e++) { l[e] = expf(l[e] - m); s += l[e]; }
            const float inv = 1.f / s;
#pragma unroll
            for (int e = 0; e < E; e++) psm[tk * 33 + e] = l[e] * inv;

            const float lse = m + logf(s);
            zsm[tk] = lse * lse;
        }
    }
    __syncthreads();

    // ---- coalesced transposed prob write ----
#pragma unroll
    for (int r = 0; r < 16; r++) {
        int idx = r * GTHREADS + tid;          // [0, 4096)
        int e = idx >> 7;
        int t = idx & (MTILE - 1);
        g_probs[(size_t)(g * E + e) * T + tt0 + t] = psm[t * 33 + e];
    }

    if (tid == 0) {
        float s = 0.f;
#pragma unroll
        for (int i = 0; i < MTILE; i++) s += zsm[i];
        g_zpart[bid] = s;
    }
}

// ---------------------------------------------------------------------------
// Kernel 2: bid<256 = top-64 selection per (g,e) -> compact g_top;
//           bid>=256 = zero dispatch half.
// ---------------------------------------------------------------------------
__global__ __launch_bounds__(NTHREADS)
void router_k2(float* __restrict__ out)
{
    const int bid = blockIdx.x;
    const int tid = threadIdx.x;

    if (bid >= SEL_BLOCKS) {
        zero_half(reinterpret_cast<uint4*>(out + GTEC), bid - SEL_BLOCKS, tid);
        return;
    }

    const float* row = g_probs + (size_t)bid * T;

    float v[16];
#pragma unroll
    for (int j = 0; j < 16; j++) v[j] = row[tid + j * NTHREADS];

    float bvv = -INFINITY; int bt = tid;
#pragma unroll
    for (int j = 0; j < 16; j++)
        if (v[j] > bvv) { bvv = v[j]; bt = j * NTHREADS + tid; }

    __shared__ float swv[8];
    __shared__ int   swt[8];
    __shared__ int   wint;

    const int lane = tid & 31;
    const int wrp  = tid >> 5;

    for (int c = 0; c < C; c++) {
        float rv = bvv; int rt = bt;
#pragma unroll
        for (int off = 16; off; off >>= 1) {
            float ov = __shfl_xor_sync(0xffffffffu, rv, off);
            int   oi = __shfl_xor_sync(0xffffffffu, rt, off);
            if (ov > rv || (ov == rv && oi < rt)) { rv = ov; rt = oi; }
        }
        if (lane == 0) { swv[wrp] = rv; swt[wrp] = rt; }
        __syncthreads();
        if (tid == 0) {
            float Rv = swv[0]; int Rt = swt[0];
#pragma unroll
            for (int w = 1; w < 8; w++)
                if (swv[w] > Rv || (swv[w] == Rv && swt[w] < Rt)) {
                    Rv = swv[w]; Rt = swt[w];
                }
            wint = Rt;
            g_topv[bid * C + c] = Rv;
            g_topt[bid * C + c] = Rt;
        }
        __syncthreads();
        const int wt = wint;
        if ((wt & (NTHREADS - 1)) == tid) {
            v[wt >> 8] = -INFINITY;
            bvv = -INFINITY; bt = tid;
#pragma unroll
            for (int j = 0; j < 16; j++)
                if (v[j] > bvv) { bvv = v[j]; bt = j * NTHREADS + tid; }
        }
    }
}

// ---------------------------------------------------------------------------
// Kernel 3: scatter the 16384 winners + z-loss finalize.
// ---------------------------------------------------------------------------
__global__ __launch_bounds__(NTHREADS)
void router_scatter(float* __restrict__ out)
{
    const int idx = blockIdx.x * NTHREADS + threadIdx.x;   // [0, 16384)

    if (idx == 0) {
        float s = 0.f;
        for (int i = 0; i < GEMM_BLOCKS; i++) s += g_zpart[i];
        out[2 * GTEC] = s / (float)GT;
    }

    const int ge = idx >> 6;
    const int c  = idx & (C - 1);
    const int g  = ge >> 5;
    const int e  = ge & (E - 1);
    const int t  = g_topt[idx];
    const float val = g_topv[idx];

    const size_t off = (((size_t)(g * T + t)) * E + e) * C + c;
    out[off]        = val;            // combine
    out[GTEC + off] = 1.0f;           // dispatch
}

__global__ void nop_k() {}

// ---------------------------------------------------------------------------
extern "C" void kernel_launch(void* const* d_in, const int* in_sizes, int n_in,
                              void* d_out, int out_size)
{
    const float* x  = (const float*)d_in[0];
    const float* Wm = (const float*)d_in[1];
    const float* bv = (const float*)d_in[2];
    float* out = (float*)d_out;

    // harness launches 2 first; 3 nops put router_k1 at global idx 5 for ncu
    nop_k<<<1, 32>>>();
    nop_k<<<1, 32>>>();
    nop_k<<<1, 32>>>();
    router_k1<<<GEMM_BLOCKS + ZERO_BLOCKS, GTHREADS>>>(x, Wm, bv, out);
    router_k2<<<SEL_BLOCKS + ZERO_BLOCKS, NTHREADS>>>(out);
    router_scatter<<<(G * E * C) / NTHREADS, NTHREADS>>>(out);
}

// round 14
// speedup vs baseline: 1.0821x; 1.0821x over previous
#include <cuda_runtime.h>
#include <cstdint>
#include <math.h>

// Problem constants
#define G  8
#define T  4096
#define H  1024
#define E  32
#define C  64
#define GT (G*T)                       // 32768 tokens
#define GTEC ((size_t)G*(size_t)T*(size_t)E*(size_t)C)   // 67,108,864

// GEMM: 128 tokens/block, 256 threads = 4 expert-groups x 64 token-pairs
// KTILE=64: 16 chunks (half the barriers of R12)
#define MTILE 128
#define KTILE 64
#define NKC   (H/KTILE)                // 16
#define GEMM_BLOCKS (GT/MTILE)         // 256
#define GTHREADS 256
#define XW 130                         // xs row stride [k][tok]
#define WW 36                          // ws row stride [k][e]

#define NTHREADS 256
#define SEL_BLOCKS  (G*E)              // 256
#define ZERO_BLOCKS 2048

// Scratch (device globals; no allocations allowed)
__device__ float g_probs[G*E*T];       // probs transposed [g][e][t], 4 MB
__device__ float g_zpart[GEMM_BLOCKS];
__device__ float g_topv[G*E*C];
__device__ int   g_topt[G*E*C];

// ---------------------------------------------------------------------------
// Kernel A: expert-split GEMM, warp-uniform expert group, 2 tokens/thread.
// Global k accumulation order (kc*64+kk ascending) identical to R12 ->
// bit-identical logits -> identical selection.
// psm/zsm overlay xs/ws (dead after mainloop) to fit 48KB static smem.
// ---------------------------------------------------------------------------
__global__ void __launch_bounds__(GTHREADS)
router_gemm(const float* __restrict__ x,   // [G,T,H]
            const float* __restrict__ Wm,  // [H,E]
            const float* __restrict__ bv)  // [E]
{
    const int bid = blockIdx.x;
    const int tid = threadIdx.x;
    const int eh  = tid >> 6;              // 0..3, uniform per warp
    const int tl2 = tid & 63;              // token-pair index 0..63

    __shared__ __align__(16) float xs[KTILE * XW];   // 64 x 130 = 33280 B
    __shared__ __align__(16) float ws[KTILE * WW];   // 64 x 36  =  9216 B
    float* psm = xs;                       // overlay: 128*33 = 4224 <= 8320 fl
    float* zsm = ws;                       // overlay: 128 <= 2304 floats

    const int gtBase = bid * MTILE;
    const int g   = gtBase >> 12;
    const int tt0 = gtBase & (T - 1);
    const float* xbase = x + (size_t)gtBase * H;

    // acc[0..3] = token0 expert-pairs, acc[4..7] = token1 expert-pairs
    unsigned long long acc[8];
#pragma unroll
    for (int i = 0; i < 8; i++) acc[i] = 0ull;

    // prefetch: x = 8 float4/thread (128 tok x 16 f4), W = 2 float4/thread
    float4 pfx[8];
    float4 pfw[2];
#pragma unroll
    for (int r = 0; r < 8; r++) {
        int h  = r >> 2;                   // k-half 0/1
        int s2 = (r & 3) * GTHREADS + tid; // [0,1024)
        int tl = s2 >> 3;
        int c  = s2 & 7;
        pfx[r] = *reinterpret_cast<const float4*>(
            xbase + (size_t)tl * H + 32 * h + c * 4);
    }
#pragma unroll
    for (int r = 0; r < 2; r++)
        pfw[r] = *reinterpret_cast<const float4*>(Wm + (r * GTHREADS + tid) * 4);

    for (int kc = 0; kc < NKC; kc++) {
        __syncthreads();                 // previous compute done
        // transpose-store x into [k][tok] (2-way conflict, same as R12)
#pragma unroll
        for (int r = 0; r < 8; r++) {
            int h  = r >> 2;
            int s2 = (r & 3) * GTHREADS + tid;
            int tl = s2 >> 3;
            int c  = s2 & 7;
            int k0 = 32 * h + 4 * c;
            xs[(k0 + 0) * XW + tl] = pfx[r].x;
            xs[(k0 + 1) * XW + tl] = pfx[r].y;
            xs[(k0 + 2) * XW + tl] = pfx[r].z;
            xs[(k0 + 3) * XW + tl] = pfx[r].w;
        }
#pragma unroll
        for (int r = 0; r < 2; r++) {
            int i = r * GTHREADS + tid;    // [0,512): k = i>>3, e4 = i&7
            *reinterpret_cast<float4*>(ws + (i >> 3) * WW + (i & 7) * 4) = pfw[r];
        }
        __syncthreads();

        if (kc + 1 < NKC) {
            const float* xn = xbase + (kc + 1) * KTILE;
#pragma unroll
            for (int r = 0; r < 8; r++) {
                int h  = r >> 2;
                int s2 = (r & 3) * GTHREADS + tid;
                int tl = s2 >> 3;
                int c  = s2 & 7;
                pfx[r] = *reinterpret_cast<const float4*>(
                    xn + (size_t)tl * H + 32 * h + c * 4);
            }
            const float* wn = Wm + (kc + 1) * KTILE * E;
#pragma unroll
            for (int r = 0; r < 2; r++)
                pfw[r] = *reinterpret_cast<const float4*>(wn + (r * GTHREADS + tid) * 4);
        }

#pragma unroll
        for (int kk = 0; kk < KTILE; kk++) {
            // x pair: LDS.64, conflict-free
            const float2 xv =
                *reinterpret_cast<const float2*>(xs + kk * XW + 2 * tl2);
            unsigned long long xx0, xx1;
            asm("mov.b64 %0, {%1,%1};" : "=l"(xx0) : "r"(__float_as_uint(xv.x)));
            asm("mov.b64 %0, {%1,%1};" : "=l"(xx1) : "r"(__float_as_uint(xv.y)));
            const ulonglong2* wr =
                reinterpret_cast<const ulonglong2*>(ws + kk * WW + (eh << 3));
            ulonglong2 w0 = wr[0];   // broadcast: warp-uniform address
            ulonglong2 w1 = wr[1];
            asm("fma.rn.f32x2 %0, %1, %2, %0;" : "+l"(acc[0]) : "l"(xx0), "l"(w0.x));
            asm("fma.rn.f32x2 %0, %1, %2, %0;" : "+l"(acc[1]) : "l"(xx0), "l"(w0.y));
            asm("fma.rn.f32x2 %0, %1, %2, %0;" : "+l"(acc[2]) : "l"(xx0), "l"(w1.x));
            asm("fma.rn.f32x2 %0, %1, %2, %0;" : "+l"(acc[3]) : "l"(xx0), "l"(w1.y));
            asm("fma.rn.f32x2 %0, %1, %2, %0;" : "+l"(acc[4]) : "l"(xx1), "l"(w0.x));
            asm("fma.rn.f32x2 %0, %1, %2, %0;" : "+l"(acc[5]) : "l"(xx1), "l"(w0.y));
            asm("fma.rn.f32x2 %0, %1, %2, %0;" : "+l"(acc[6]) : "l"(xx1), "l"(w1.x));
            asm("fma.rn.f32x2 %0, %1, %2, %0;" : "+l"(acc[7]) : "l"(xx1), "l"(w1.y));
        }
    }

    // xs/ws are dead from here; psm/zsm overlay them (barrier first!)
    __syncthreads();

    // ---- gather raw logits to smem (bit-exact values) ----
    {
        const int t0 = 2 * tl2, t1 = 2 * tl2 + 1;
#pragma unroll
        for (int i = 0; i < 4; i++) {
            float2 f0 = *reinterpret_cast<float2*>(&acc[i]);
            float2 f1 = *reinterpret_cast<float2*>(&acc[4 + i]);
            psm[t0 * 33 + (eh << 3) + 2*i]     = f0.x;
            psm[t0 * 33 + (eh << 3) + 2*i + 1] = f0.y;
            psm[t1 * 33 + (eh << 3) + 2*i]     = f1.x;
            psm[t1 * 33 + (eh << 3) + 2*i + 1] = f1.y;
        }
    }
    __syncthreads();

    // ---- eh==0 threads: exact R5/R12 softmax sequence, 2 tokens each ----
    if (eh == 0) {
#pragma unroll
        for (int u = 0; u < 2; u++) {
            const int tk = 2 * tl2 + u;
            float l[E];
#pragma unroll
            for (int e = 0; e < E; e++) l[e] = psm[tk * 33 + e];
#pragma unroll
            for (int e = 0; e < E; e++) l[e] += __ldg(&bv[e]);

            float m = l[0];
#pragma unroll
            for (int e = 1; e < E; e++) m = fmaxf(m, l[e]);
            float s = 0.f;
#pragma unroll
            for (int e = 0; e < E; e++) { l[e] = expf(l[e] - m); s += l[e]; }
            const float inv = 1.f / s;
#pragma unroll
            for (int e = 0; e < E; e++) psm[tk * 33 + e] = l[e] * inv;

            const float lse = m + logf(s);
            zsm[tk] = lse * lse;
        }
    }
    __syncthreads();

    // ---- coalesced transposed prob write: [e][t] runs of 128 ----
#pragma unroll
    for (int r = 0; r < 16; r++) {
        int idx = r * GTHREADS + tid;          // [0, 4096)
        int e = idx >> 7;
        int t = idx & (MTILE - 1);
        g_probs[(size_t)(g * E + e) * T + tt0 + t] = psm[t * 33 + e];
    }

    if (tid == 0) {
        float s = 0.f;
#pragma unroll
        for (int i = 0; i < MTILE; i++) s += zsm[i];
        g_zpart[bid] = s;
    }
}

// ---------------------------------------------------------------------------
// Kernel B: blocks [0,256) = top-64 selection per (g,e) -> compact g_top
//           blocks [256, 2304) = grid-stride streaming zero fill of out.
// ---------------------------------------------------------------------------
__global__ __launch_bounds__(NTHREADS)
void router_zero_sel(float* __restrict__ out)
{
    const int bid = blockIdx.x;
    const int tid = threadIdx.x;

    if (bid >= SEL_BLOCKS) {
        uint4 z; z.x = 0u; z.y = 0u; z.z = 0u; z.w = 0u;
        uint4* o4 = reinterpret_cast<uint4*>(out);
        const size_t n4 = (2*GTEC) / 4;                    // 33,554,432
        size_t i = (size_t)(bid - SEL_BLOCKS) * NTHREADS + tid;
        const size_t stride = (size_t)ZERO_BLOCKS * NTHREADS;
        for (; i < n4; i += stride) __stcs(o4 + i, z);
        return;
    }

    const float* row = g_probs + (size_t)bid * T;

    float v[16];
#pragma unroll
    for (int j = 0; j < 16; j++) v[j] = row[tid + j * NTHREADS];

    float bvv = -INFINITY; int bt = tid;
#pragma unroll
    for (int j = 0; j < 16; j++)
        if (v[j] > bvv) { bvv = v[j]; bt = j * NTHREADS + tid; }

    __shared__ float swv[8];
    __shared__ int   swt[8];
    __shared__ int   wint;

    const int lane = tid & 31;
    const int wrp  = tid >> 5;

    for (int c = 0; c < C; c++) {
        float rv = bvv; int rt = bt;
#pragma unroll
        for (int off = 16; off; off >>= 1) {
            float ov = __shfl_xor_sync(0xffffffffu, rv, off);
            int   oi = __shfl_xor_sync(0xffffffffu, rt, off);
            if (ov > rv || (ov == rv && oi < rt)) { rv = ov; rt = oi; }
        }
        if (lane == 0) { swv[wrp] = rv; swt[wrp] = rt; }
        __syncthreads();
        if (tid == 0) {
            float Rv = swv[0]; int Rt = swt[0];
#pragma unroll
            for (int w = 1; w < 8; w++)
                if (swv[w] > Rv || (swv[w] == Rv && swt[w] < Rt)) {
                    Rv = swv[w]; Rt = swt[w];
                }
            wint = Rt;
            g_topv[bid * C + c] = Rv;
            g_topt[bid * C + c] = Rt;
        }
        __syncthreads();
        const int wt = wint;
        if ((wt & (NTHREADS - 1)) == tid) {
            v[wt >> 8] = -INFINITY;
            bvv = -INFINITY; bt = tid;
#pragma unroll
            for (int j = 0; j < 16; j++)
                if (v[j] > bvv) { bvv = v[j]; bt = j * NTHREADS + tid; }
        }
    }
}

// ---------------------------------------------------------------------------
// Kernel C: scatter the 16384 winners + z-loss finalize.
// ---------------------------------------------------------------------------
__global__ __launch_bounds__(NTHREADS)
void router_scatter(float* __restrict__ out)
{
    const int idx = blockIdx.x * NTHREADS + threadIdx.x;   // [0, 16384)

    if (idx == 0) {
        float s = 0.f;
        for (int i = 0; i < GEMM_BLOCKS; i++) s += g_zpart[i];
        out[2 * GTEC] = s / (float)GT;
    }

    const int ge = idx >> 6;
    const int c  = idx & (C - 1);
    const int g  = ge >> 5;
    const int e  = ge & (E - 1);
    const int t  = g_topt[idx];
    const float val = g_topv[idx];

    const size_t off = (((size_t)(g * T + t)) * E + e) * C + c;
    out[off]        = val;            // combine
    out[GTEC + off] = 1.0f;           // dispatch
}

// ---------------------------------------------------------------------------
extern "C" void kernel_launch(void* const* d_in, const int* in_sizes, int n_in,
                              void* d_out, int out_size)
{
    const float* x  = (const float*)d_in[0];
    const float* Wm = (const float*)d_in[1];
    const float* bv = (const float*)d_in[2];
    float* out = (float*)d_out;

    // 3 launches/call: ncu idx-5 capture = router_gemm of the 2nd replay
    router_gemm<<<GEMM_BLOCKS, GTHREADS>>>(x, Wm, bv);
    router_zero_sel<<<SEL_BLOCKS + ZERO_BLOCKS, NTHREADS>>>(out);
    router_scatter<<<(G * E * C) / NTHREADS, NTHREADS>>>(out);
}